// round 11
// baseline (speedup 1.0000x reference)
#include <cuda_runtime.h>
#include <cuda_bf16.h>
#include <math.h>

// ---------------------------------------------------------------------------
// MotionGenerator_RNN  (N=64, A=128, MO=126, LX=96, H=1024, S=32, P=2, B=16,
//                       BL=32, T=448, L=512, IN=382, GIN=1406)
// Single persistent kernel (1 graph node). 148 CTAs x 256 threads.
// fp32, smem-tiled 64x16 GEMM tiles, register-staged double buffering,
// monotonic-ticket grid barriers between phases.
// ---------------------------------------------------------------------------

#define NCTA 148
#define NTHR 256
#define TT   448
#define OFF_ZMU (64 * 126 * 448)
#define OFF_ZLV (OFF_ZMU + 64 * 32 * 448)

// ------------------------- device scratch (static, no allocs) ---------------
__device__ float g_xfix[(size_t)TT * 64 * 256];  // [t][n][aud128|lxm96|style32]
__device__ float g_t1[64 * 1024];
__device__ float g_t2[64 * 1024];
__device__ float g_cell[64 * 2048];
__device__ float g_h0[64 * 1024];
__device__ float g_h1[64 * 1024];
__device__ float g_premo[64 * 126];
__device__ float g_ine[64 * 1024];
__device__ float g_gi0a[64 * 3072];
__device__ float g_gi0b[64 * 3072];
__device__ float g_gh0[64 * 3072];
__device__ float g_gi1[64 * 3072];
__device__ float g_gh1[64 * 3072];

// grid barrier state: both counters are monotonic forever (graph-replay safe)
__device__ unsigned long long g_cnt;   // arrival tickets
__device__ unsigned long long g_gen;   // completed generations

// ------------------------- helpers ------------------------------------------
__device__ __forceinline__ float gelu_f(float x) {
    return 0.5f * x * (1.0f + erff(x * 0.70710678118654752f));
}
__device__ __forceinline__ float sigm_f(float x) {
    return 1.0f / (1.0f + expf(-x));
}

// Monotonic-ticket grid barrier. Ticket a -> this barrier completes generation
// a/NCTA + 1. No counter resets => no read-before-arrive race, and state is
// consistent across graph replays. Reader-side __threadfence() (gpu scope)
// emits CCTL.IVALL on sm_103a -> L1D invalidated -> plain loads after the
// barrier observe other SMs' writes.
__device__ __forceinline__ void gbar() {
    __syncthreads();
    if (threadIdx.x == 0) {
        __threadfence();  // release my CTA's writes
        unsigned long long a = atomicAdd(&g_cnt, 1ULL);
        unsigned long long target = a / NCTA + 1ULL;
        if ((a % NCTA) == (NCTA - 1)) {
            atomicAdd(&g_gen, 1ULL);
        } else {
            while (*(volatile unsigned long long*)&g_gen < target) {
                __nanosleep(64);
            }
        }
        __threadfence();  // acquire: invalidate L1D before consuming
    }
    __syncthreads();
}

// ------------------------- tiled 64x16 GEMM ---------------------------------
// Computes out[0..63][col0..col0+15] = act(X(64 x klen) @ W[kbase.., col0..] + bias)
// X fetched via MODE:
//   0: A[r*1024 + k]                                   (activations, lda=1024)
//   1: k<126 -> premo(A)[r*126+k] ; else xfix(Aux1)[r*256 + k-126]
//   2: k<1024 -> ine(A) ; k<1150 -> premo(Aux1) ; else xfix(Aux2)
//   3: k<126 -> mo(A)[(r*126+k)*512+31] ; else lxm(Aux1)[(r*96+k-126)*16]
struct TileJob {
    const float* A;
    const float* Aux1;
    const float* Aux2;
    int kbase;
    int klen;
    const float* W;     // row-major [K_total x ldw]
    int ldw;
    const float* bias;  // may be nullptr
    float* out;
    int ldo;
    int col0;
    int act;            // 1 = gelu
};

template <int MODE>
__device__ __forceinline__ float fA(const TileJob& j, int r, int k) {
    if (MODE == 0) return j.A[r * 1024 + k];
    if (MODE == 1) {
        return (k < 126) ? j.A[r * 126 + k] : j.Aux1[r * 256 + (k - 126)];
    }
    if (MODE == 2) {
        if (k < 1024) return j.A[r * 1024 + k];
        int kk = k - 1024;
        return (kk < 126) ? j.Aux1[r * 126 + kk] : j.Aux2[r * 256 + (kk - 126)];
    }
    // MODE 3
    return (k < 126) ? j.A[(r * 126 + k) * 512 + 31]
                     : j.Aux1[(r * 96 + (k - 126)) * 16];
}

// smem: Xs double buffer 2*32*65 floats (padded: stores/loads conflict-free),
//       Ws double buffer 2*32*16 floats.
template <int MODE>
__device__ __noinline__ void run_tile(const TileJob& j, float* Xs, float* Ws) {
    const int tid = threadIdx.x;
    const int rw = tid >> 3;          // rows rw, rw+32
    const int c2 = (tid & 7) * 2;     // cols c2, c2+1 (within 16-col tile)
    const int nit = (j.klen + 31) >> 5;

    float a00 = 0.f, a01 = 0.f, a10 = 0.f, a11 = 0.f;
    float xr[8], wr[2];

    auto load_stage = [&](int it) {
#pragma unroll
        for (int q = 0; q < 8; q++) {
            int e = tid + q * 256;
            int r = e >> 5, kk = e & 31;
            int k = it * 32 + kk;
            xr[q] = (k < j.klen) ? fA<MODE>(j, r, j.kbase + k) : 0.f;
        }
#pragma unroll
        for (int q = 0; q < 2; q++) {
            int e = tid + q * 256;
            int kk = e >> 4, cc = e & 15;
            int k = it * 32 + kk;
            wr[q] = (k < j.klen)
                        ? j.W[(size_t)(j.kbase + k) * j.ldw + j.col0 + cc]
                        : 0.f;
        }
    };
    auto store_stage = [&](int buf) {
        float* xb = Xs + buf * (32 * 65);
        float* wb = Ws + buf * (32 * 16);
#pragma unroll
        for (int q = 0; q < 8; q++) {
            int e = tid + q * 256;
            int r = e >> 5, kk = e & 31;
            xb[kk * 65 + r] = xr[q];
        }
#pragma unroll
        for (int q = 0; q < 2; q++) {
            int e = tid + q * 256;
            int kk = e >> 4, cc = e & 15;
            wb[kk * 16 + cc] = wr[q];
        }
    };

    load_stage(0);
    __syncthreads();          // protect previous tile's smem readers
    store_stage(0);

    int buf = 0;
    for (int it = 0; it < nit; it++) {
        __syncthreads();      // smem[buf] fully staged
        if (it + 1 < nit) load_stage(it + 1);   // overlap gmem with compute
        const float* xb = Xs + buf * (32 * 65);
        const float* wb = Ws + buf * (32 * 16);
#pragma unroll
        for (int kk = 0; kk < 32; kk++) {
            float x0 = xb[kk * 65 + rw];
            float x1 = xb[kk * 65 + rw + 32];
            float2 w = *reinterpret_cast<const float2*>(wb + kk * 16 + c2);
            a00 += x0 * w.x; a01 += x0 * w.y;
            a10 += x1 * w.x; a11 += x1 * w.y;
        }
        if (it + 1 < nit) store_stage(buf ^ 1);
        buf ^= 1;
    }

    float b0 = j.bias ? j.bias[j.col0 + c2] : 0.f;
    float b1 = j.bias ? j.bias[j.col0 + c2 + 1] : 0.f;
    float v00 = a00 + b0, v01 = a01 + b1;
    float v10 = a10 + b0, v11 = a11 + b1;
    if (j.act) {
        v00 = gelu_f(v00); v01 = gelu_f(v01);
        v10 = gelu_f(v10); v11 = gelu_f(v11);
    }
    j.out[rw * j.ldo + j.col0 + c2]            = v00;
    j.out[rw * j.ldo + j.col0 + c2 + 1]        = v01;
    j.out[(rw + 32) * j.ldo + j.col0 + c2]     = v10;
    j.out[(rw + 32) * j.ldo + j.col0 + c2 + 1] = v11;
}

// ------------------------- the persistent kernel ----------------------------
__global__ __launch_bounds__(NTHR, 1) void scan_kernel(
    const float* __restrict__ aud, const float* __restrict__ mo,
    const float* __restrict__ lxm, const int* __restrict__ vid,
    const float* __restrict__ eps, const float* __restrict__ csi_w0,
    const float* __restrict__ csi_b0, const float* __restrict__ csi_w1,
    const float* __restrict__ csi_b1, const float* __restrict__ csi_w2,
    const float* __restrict__ csi_b2, const float* __restrict__ spk,
    const float* __restrict__ mu_w, const float* __restrict__ mu_b,
    const float* __restrict__ lv_w, const float* __restrict__ lv_b,
    const float* __restrict__ emb_w, const float* __restrict__ emb_b,
    const float* __restrict__ wih0, const float* __restrict__ whh0,
    const float* __restrict__ bih0, const float* __restrict__ bhh0,
    const float* __restrict__ wih1, const float* __restrict__ whh1,
    const float* __restrict__ bih1, const float* __restrict__ bhh1,
    const float* __restrict__ ln_g, const float* __restrict__ ln_b,
    const float* __restrict__ pred_w, const float* __restrict__ pred_b,
    float* __restrict__ out)
{
    __shared__ float pool[2 * 32 * 65 + 2 * 32 * 16];  // 5184 floats
    float* Xs = pool;
    float* Ws = pool + 2 * 32 * 65;

    const int cta = blockIdx.x;
    const int tid = threadIdx.x;

    // ---------------- P0: prelude (xfix + z_mu/z_lv) + P1: CSI layer 0 ------
    {
        const long total = 64L * 256 * 448;
        for (long i = (long)cta * NTHR + tid; i < total; i += (long)NCTA * NTHR) {
            int t = (int)(i % 448);
            long rem = i / 448;
            int cidx = (int)(rem & 255);
            int n = (int)(rem >> 8);
            int blk1 = (t >> 5) + 1;
            float v;
            if (cidx < 128) {
                v = aud[((size_t)n * 128 + cidx) * 448 + t];
            } else if (cidx < 224) {
                v = lxm[(n * 96 + (cidx - 128)) * 16 + blk1];
            } else {
                int s = cidx - 224;
                int vi = vid[n * 16 + blk1];
                const float* z = spk + vi * 32;
                float zmu = mu_b[s], zlv = lv_b[s];
#pragma unroll
                for (int k = 0; k < 32; k++) {
                    float zk = z[k];
                    zmu += zk * mu_w[k * 32 + s];
                    zlv += zk * lv_w[k * 32 + s];
                }
                out[OFF_ZMU + ((size_t)n * 32 + s) * 448 + t] = zmu;
                out[OFF_ZLV + ((size_t)n * 32 + s) * 448 + t] = zlv;
                v = zmu + eps[((size_t)t * 64 + n) * 32 + s] * expf(0.5f * zlv);
            }
            g_xfix[((size_t)t * 64 + n) * 256 + cidx] = v;
        }
        // CSI layer 0: 64 tiles, mode 3 (gathers mo/lxm)
        for (int tile = cta; tile < 64; tile += NCTA) {
            TileJob j = {mo, lxm, nullptr, 0, 222, csi_w0, 1024, csi_b0,
                         g_t1, 1024, tile * 16, 1};
            run_tile<3>(j, Xs, Ws);
        }
    }
    gbar();

    // ---------------- P2: CSI layer 1 --------------------------------------
    for (int tile = cta; tile < 64; tile += NCTA) {
        TileJob j = {g_t1, nullptr, nullptr, 0, 1024, csi_w1, 1024, csi_b1,
                     g_t2, 1024, tile * 16, 1};
        run_tile<0>(j, Xs, Ws);
    }
    gbar();

    // ---------------- P3: CSI layer 2 (cell states) -------------------------
    for (int tile = cta; tile < 128; tile += NCTA) {
        TileJob j = {g_t2, nullptr, nullptr, 0, 1024, csi_w2, 2048, csi_b2,
                     g_cell, 2048, tile * 16, 0};
        run_tile<0>(j, Xs, Ws);
    }
    gbar();

    // ---------------- P4: init h0/h1/premo ----------------------------------
    for (int i = cta * NTHR + tid; i < 64 * 1024; i += NCTA * NTHR) {
        int r = i >> 10, c = i & 1023;
        g_h0[i] = g_cell[r * 2048 + c];
        g_h1[i] = g_cell[r * 2048 + 1024 + c];
    }
    for (int i = cta * NTHR + tid; i < 64 * 126; i += NCTA * NTHR) {
        g_premo[i] = mo[(size_t)i * 512 + 31];
    }
    gbar();

    // ---------------- time loop ---------------------------------------------
    for (int t = 0; t < TT; t++) {
        const float* xfix_t = g_xfix + (size_t)t * 64 * 256;

        // Phase A: gh0 = h0 @ whh0 + bhh0 (192 tiles) ; ine (64 tiles)
        for (int tile = cta; tile < 256; tile += NCTA) {
            if (tile < 192) {
                TileJob j = {g_h0, nullptr, nullptr, 0, 1024, whh0, 3072, bhh0,
                             g_gh0, 3072, tile * 16, 0};
                run_tile<0>(j, Xs, Ws);
            } else {
                TileJob j = {g_premo, xfix_t, nullptr, 0, 382, emb_w, 1024,
                             emb_b, g_ine, 1024, (tile - 192) * 16, 1};
                run_tile<1>(j, Xs, Ws);
            }
        }
        gbar();

        // Phase B: gi0 = gx @ wih0 + bih0, K split 704/702 for balance
        for (int tile = cta; tile < 384; tile += NCTA) {
            if (tile < 192) {
                TileJob j = {g_ine, g_premo, xfix_t, 0, 704, wih0, 3072, bih0,
                             g_gi0a, 3072, tile * 16, 0};
                run_tile<2>(j, Xs, Ws);
            } else {
                TileJob j = {g_ine, g_premo, xfix_t, 704, 702, wih0, 3072,
                             nullptr, g_gi0b, 3072, (tile - 192) * 16, 0};
                run_tile<2>(j, Xs, Ws);
            }
        }
        gbar();

        // Phase C: GRU0 gates -> h0 (in place)
        for (int i = cta * NTHR + tid; i < 64 * 1024; i += NCTA * NTHR) {
            int r = i >> 10, c = i & 1023;
            const float* ga = g_gi0a + r * 3072;
            const float* gb = g_gi0b + r * 3072;
            const float* gh = g_gh0 + r * 3072;
            float rg = sigm_f(ga[c] + gb[c] + gh[c]);
            float zg = sigm_f(ga[c + 1024] + gb[c + 1024] + gh[c + 1024]);
            float ng = tanhf(ga[c + 2048] + gb[c + 2048] + rg * gh[c + 2048]);
            g_h0[i] = (1.f - zg) * ng + zg * g_h0[i];
        }
        gbar();

        // Phase D: gi1 = h0 @ wih1 + bih1 ; gh1 = h1 @ whh1 + bhh1
        for (int tile = cta; tile < 384; tile += NCTA) {
            if (tile < 192) {
                TileJob j = {g_h0, nullptr, nullptr, 0, 1024, wih1, 3072, bih1,
                             g_gi1, 3072, tile * 16, 0};
                run_tile<0>(j, Xs, Ws);
            } else {
                TileJob j = {g_h1, nullptr, nullptr, 0, 1024, whh1, 3072, bhh1,
                             g_gh1, 3072, (tile - 192) * 16, 0};
                run_tile<0>(j, Xs, Ws);
            }
        }
        gbar();

        // Phase E: GRU1 gates + layernorm + pred (64 row-CTAs)
        if (cta < 64) {
            int r = cta;
            float* xs = pool;          // 1024
            float* red = pool + 1024;  // 256
            const float* gir = g_gi1 + r * 3072;
            const float* ghr = g_gh1 + r * 3072;
            float* hr = g_h1 + r * 1024;

            float lsum = 0.f;
            for (int c = tid; c < 1024; c += NTHR) {
                float rg = sigm_f(gir[c] + ghr[c]);
                float zg = sigm_f(gir[c + 1024] + ghr[c + 1024]);
                float ng = tanhf(gir[c + 2048] + rg * ghr[c + 2048]);
                float hnew = (1.f - zg) * ng + zg * hr[c];
                hr[c] = hnew;
                xs[c] = hnew;
                lsum += hnew;
            }
            red[tid] = lsum;
            __syncthreads();
            for (int s = 128; s > 0; s >>= 1) {
                if (tid < s) red[tid] += red[tid + s];
                __syncthreads();
            }
            float mean = red[0] * (1.f / 1024.f);
            __syncthreads();
            float lv = 0.f;
            for (int c = tid; c < 1024; c += NTHR) {
                float d = xs[c] - mean;
                lv += d * d;
            }
            red[tid] = lv;
            __syncthreads();
            for (int s = 128; s > 0; s >>= 1) {
                if (tid < s) red[tid] += red[tid + s];
                __syncthreads();
            }
            float inv = rsqrtf(red[0] * (1.f / 1024.f) + 1e-5f);
            __syncthreads();
            for (int c = tid; c < 1024; c += NTHR)
                xs[c] = (xs[c] - mean) * inv * ln_g[c] + ln_b[c];
            __syncthreads();

            if (tid < 126) {
                float s0 = 0.f, s1 = 0.f, s2 = 0.f, s3 = 0.f;
                for (int k = 0; k < 1024; k += 4) {
                    s0 += xs[k + 0] * pred_w[(k + 0) * 126 + tid];
                    s1 += xs[k + 1] * pred_w[(k + 1) * 126 + tid];
                    s2 += xs[k + 2] * pred_w[(k + 2) * 126 + tid];
                    s3 += xs[k + 3] * pred_w[(k + 3) * 126 + tid];
                }
                float s = pred_b[tid] + ((s0 + s1) + (s2 + s3));
                g_premo[r * 126 + tid] = s;
                out[((size_t)r * 126 + tid) * 448 + t] = s;
            }
        }
        gbar();
    }
}

// ---------------------------------------------------------------------------
extern "C" void kernel_launch(void* const* d_in, const int* in_sizes, int n_in,
                              void* d_out, int out_size) {
    scan_kernel<<<NCTA, NTHR>>>(
        (const float*)d_in[0],  (const float*)d_in[1],  (const float*)d_in[2],
        (const int*)  d_in[3],  (const float*)d_in[4],  (const float*)d_in[5],
        (const float*)d_in[6],  (const float*)d_in[7],  (const float*)d_in[8],
        (const float*)d_in[9],  (const float*)d_in[10], (const float*)d_in[11],
        (const float*)d_in[12], (const float*)d_in[13], (const float*)d_in[14],
        (const float*)d_in[15], (const float*)d_in[16], (const float*)d_in[17],
        (const float*)d_in[18], (const float*)d_in[19], (const float*)d_in[20],
        (const float*)d_in[21], (const float*)d_in[22], (const float*)d_in[23],
        (const float*)d_in[24], (const float*)d_in[25], (const float*)d_in[26],
        (const float*)d_in[27], (const float*)d_in[28], (const float*)d_in[29],
        (float*)d_out);
}

// round 13
// speedup vs baseline: 2.7890x; 2.7890x over previous
#include <cuda_runtime.h>
#include <cuda_bf16.h>
#include <math.h>

// ---------------------------------------------------------------------------
// MotionGenerator_RNN  (N=64, A=128, MO=126, LX=96, H=1024, S=32, P=2, B=16,
//                       BL=32, T=448, L=512, IN=382, GIN=1406)
// Single persistent kernel. 148 CTAs x 256 threads. fp32 with packed f32x2
// FMA (FFMA2), 64x64 smem-tiled GEMM, 4x4 thread tile, double buffering,
// monotonic-ticket grid barriers.
// ---------------------------------------------------------------------------

#define NCTA 148
#define NTHR 256
#define TT   448
#define OFF_ZMU (64 * 126 * 448)
#define OFF_ZLV (OFF_ZMU + 64 * 32 * 448)

// ------------------------- device scratch (static, no allocs) ---------------
__device__ float g_xfix[(size_t)TT * 64 * 256];  // [t][n][aud128|lxm96|style32]
__device__ float g_t1[64 * 1024];
__device__ float g_t2[64 * 1024];
__device__ float g_cell[64 * 2048];
__device__ float g_h0[64 * 1024];
__device__ float g_h1[64 * 1024];
__device__ float g_premo[64 * 126];
__device__ float g_ine[64 * 1024];
__device__ float g_gi0a[64 * 3072];
__device__ float g_gi0b[64 * 3072];
__device__ float g_gi0c[64 * 3072];
__device__ float g_gh0a[64 * 3072];
__device__ float g_gh0b[64 * 3072];
__device__ float g_gi1a[64 * 3072];
__device__ float g_gi1b[64 * 3072];
__device__ float g_gi1c[64 * 3072];
__device__ float g_gh1a[64 * 3072];
__device__ float g_gh1b[64 * 3072];
__device__ float g_gh1c[64 * 3072];

// grid barrier state: both counters monotonic forever (graph-replay safe)
__device__ unsigned long long g_cnt;
__device__ unsigned long long g_gen;

// ------------------------- helpers ------------------------------------------
__device__ __forceinline__ float gelu_f(float x) {
    return 0.5f * x * (1.0f + erff(x * 0.70710678118654752f));
}
__device__ __forceinline__ float sigm_f(float x) {
    return 1.0f / (1.0f + expf(-x));
}
__device__ __forceinline__ unsigned long long splat2(float x) {
    unsigned long long r;
    unsigned u = __float_as_uint(x);
    asm("mov.b64 %0, {%1, %1};" : "=l"(r) : "r"(u));
    return r;
}
__device__ __forceinline__ void fma2(unsigned long long& acc,
                                     unsigned long long a, unsigned long long b) {
    asm("fma.rn.f32x2 %0, %1, %2, %0;" : "+l"(acc) : "l"(a), "l"(b));
}

// Monotonic-ticket grid barrier (proven in R10/R11 pass).
__device__ __forceinline__ void gbar() {
    __syncthreads();
    if (threadIdx.x == 0) {
        __threadfence();
        unsigned long long a = atomicAdd(&g_cnt, 1ULL);
        unsigned long long target = a / NCTA + 1ULL;
        if ((a % NCTA) == (NCTA - 1)) {
            atomicAdd(&g_gen, 1ULL);
        } else {
            while (*(volatile unsigned long long*)&g_gen < target) {
                __nanosleep(64);
            }
        }
        __threadfence();
    }
    __syncthreads();
}

// ------------------------- tiled 64x64 GEMM (f32x2 core) --------------------
// out[0..63][col0..col0+63] (+)= X(64 x klen, from kbase) @ W + bias, opt gelu.
// MODE selects the A fetch (virtual concatenations):
//   0: A[r*1024 + k]
//   1: k<126 -> premo(A)[r*126+k] ; else xfix(Aux1)[r*256 + k-126]
//   2: k<1024 -> ine(A)[r*1024+k]; k<1150 -> premo(Aux1); else xfix(Aux2)
//   3: k<126 -> mo(A)[(r*126+k)*512+31] ; else lxm(Aux1)[(r*96+k-126)*16]
struct TileJob {
    const float* A;
    const float* Aux1;
    const float* Aux2;
    int kbase;
    int klen;
    const float* W;     // row-major [K_total x ldw]
    int ldw;
    const float* bias;  // nullptr for non-first K-splits
    float* out;
    int ldo;
    int col0;
    int act;            // 1 = gelu (only on full-K jobs)
};

template <int MODE>
__device__ __forceinline__ float fA(const TileJob& j, int r, int k) {
    if (MODE == 0) return j.A[r * 1024 + k];
    if (MODE == 1) {
        return (k < 126) ? j.A[r * 126 + k] : j.Aux1[r * 256 + (k - 126)];
    }
    if (MODE == 2) {
        if (k < 1024) return j.A[r * 1024 + k];
        int kk = k - 1024;
        return (kk < 126) ? j.Aux1[r * 126 + kk] : j.Aux2[r * 256 + (kk - 126)];
    }
    return (k < 126) ? j.A[(r * 126 + k) * 512 + 31]
                     : j.Aux1[(r * 96 + (k - 126)) * 16];
}

#define XPITCH 68              // 64 rows + 4 pad (16B-aligned rows, mild STS conflicts)
#define WPITCH 64
#define XBUF   (32 * XPITCH)   // 2176 floats
#define WBUF   (32 * WPITCH)   // 2048 floats

template <int MODE>
__device__ __noinline__ void run_tile(const TileJob& j, float* Xs, float* Ws) {
    const int tid = threadIdx.x;
    const int rg4 = (tid >> 4) << 2;   // row base 0..60
    const int cg4 = (tid & 15) << 2;   // col base 0..60
    const int nit = (j.klen + 31) >> 5;

    unsigned long long acc[4][2] = {};
    float xr[8], wr[8];

    auto load_stage = [&](int it) {
#pragma unroll
        for (int q = 0; q < 8; q++) {
            int e = tid + q * 256;
            int r = e >> 5, kk = e & 31;
            int k = it * 32 + kk;
            xr[q] = (k < j.klen) ? fA<MODE>(j, r, j.kbase + k) : 0.f;
        }
#pragma unroll
        for (int q = 0; q < 8; q++) {
            int e = tid + q * 256;
            int kk = e >> 6, cc = e & 63;
            int k = it * 32 + kk;
            wr[q] = (k < j.klen)
                        ? j.W[(size_t)(j.kbase + k) * j.ldw + j.col0 + cc]
                        : 0.f;
        }
    };
    auto store_stage = [&](int buf) {
        float* xb = Xs + buf * XBUF;
        float* wb = Ws + buf * WBUF;
#pragma unroll
        for (int q = 0; q < 8; q++) {
            int e = tid + q * 256;
            int r = e >> 5, kk = e & 31;
            xb[kk * XPITCH + r] = xr[q];
        }
#pragma unroll
        for (int q = 0; q < 8; q++) {
            int e = tid + q * 256;
            int kk = e >> 6, cc = e & 63;
            wb[kk * WPITCH + cc] = wr[q];
        }
    };

    load_stage(0);
    __syncthreads();           // protect previous tile's smem readers
    store_stage(0);

    int buf = 0;
    for (int it = 0; it < nit; it++) {
        __syncthreads();       // smem[buf] fully staged
        if (it + 1 < nit) load_stage(it + 1);
        const float* xb = Xs + buf * XBUF;
        const float* wb = Ws + buf * WBUF;
#pragma unroll
        for (int kk = 0; kk < 32; kk++) {
            float4 xv = *reinterpret_cast<const float4*>(xb + kk * XPITCH + rg4);
            ulonglong2 wv = *reinterpret_cast<const ulonglong2*>(wb + kk * WPITCH + cg4);
            unsigned long long x0 = splat2(xv.x), x1 = splat2(xv.y);
            unsigned long long x2 = splat2(xv.z), x3 = splat2(xv.w);
            fma2(acc[0][0], x0, wv.x); fma2(acc[0][1], x0, wv.y);
            fma2(acc[1][0], x1, wv.x); fma2(acc[1][1], x1, wv.y);
            fma2(acc[2][0], x2, wv.x); fma2(acc[2][1], x2, wv.y);
            fma2(acc[3][0], x3, wv.x); fma2(acc[3][1], x3, wv.y);
        }
        if (it + 1 < nit) store_stage(buf ^ 1);
        buf ^= 1;
    }

#pragma unroll
    for (int i = 0; i < 4; i++) {
        int row = rg4 + i;
#pragma unroll
        for (int p = 0; p < 2; p++) {
            unsigned lo, hi;
            asm("mov.b64 {%0,%1}, %2;" : "=r"(lo), "=r"(hi) : "l"(acc[i][p]));
            float v0 = __uint_as_float(lo), v1 = __uint_as_float(hi);
            int cb = j.col0 + cg4 + p * 2;
            if (j.bias) { v0 += j.bias[cb]; v1 += j.bias[cb + 1]; }
            if (j.act)  { v0 = gelu_f(v0); v1 = gelu_f(v1); }
            *reinterpret_cast<float2*>(j.out + (size_t)row * j.ldo + cb) =
                make_float2(v0, v1);
        }
    }
}

// ------------------------- the persistent kernel ----------------------------
__global__ __launch_bounds__(NTHR, 1) void scan_kernel(
    const float* __restrict__ aud, const float* __restrict__ mo,
    const float* __restrict__ lxm, const int* __restrict__ vid,
    const float* __restrict__ eps, const float* __restrict__ csi_w0,
    const float* __restrict__ csi_b0, const float* __restrict__ csi_w1,
    const float* __restrict__ csi_b1, const float* __restrict__ csi_w2,
    const float* __restrict__ csi_b2, const float* __restrict__ spk,
    const float* __restrict__ mu_w, const float* __restrict__ mu_b,
    const float* __restrict__ lv_w, const float* __restrict__ lv_b,
    const float* __restrict__ emb_w, const float* __restrict__ emb_b,
    const float* __restrict__ wih0, const float* __restrict__ whh0,
    const float* __restrict__ bih0, const float* __restrict__ bhh0,
    const float* __restrict__ wih1, const float* __restrict__ whh1,
    const float* __restrict__ bih1, const float* __restrict__ bhh1,
    const float* __restrict__ ln_g, const float* __restrict__ ln_b,
    const float* __restrict__ pred_w, const float* __restrict__ pred_b,
    float* __restrict__ out)
{
    __shared__ __align__(16) float pool[2 * XBUF + 2 * WBUF];  // 8448 floats
    float* Xs = pool;
    float* Ws = pool + 2 * XBUF;

    const int cta = blockIdx.x;
    const int tid = threadIdx.x;

    // ---------------- P0: prelude (xfix + z_mu/z_lv) + CSI layer 0 ----------
    {
        const long total = 64L * 256 * 448;
        for (long i = (long)cta * NTHR + tid; i < total; i += (long)NCTA * NTHR) {
            int t = (int)(i % 448);
            long rem = i / 448;
            int cidx = (int)(rem & 255);
            int n = (int)(rem >> 8);
            int blk1 = (t >> 5) + 1;
            float v;
            if (cidx < 128) {
                v = aud[((size_t)n * 128 + cidx) * 448 + t];
            } else if (cidx < 224) {
                v = lxm[(n * 96 + (cidx - 128)) * 16 + blk1];
            } else {
                int s = cidx - 224;
                int vi = vid[n * 16 + blk1];
                const float* z = spk + vi * 32;
                float zmu = mu_b[s], zlv = lv_b[s];
#pragma unroll
                for (int k = 0; k < 32; k++) {
                    float zk = z[k];
                    zmu += zk * mu_w[k * 32 + s];
                    zlv += zk * lv_w[k * 32 + s];
                }
                out[OFF_ZMU + ((size_t)n * 32 + s) * 448 + t] = zmu;
                out[OFF_ZLV + ((size_t)n * 32 + s) * 448 + t] = zlv;
                v = zmu + eps[((size_t)t * 64 + n) * 32 + s] * expf(0.5f * zlv);
            }
            g_xfix[((size_t)t * 64 + n) * 256 + cidx] = v;
        }
        for (int tile = cta; tile < 16; tile += NCTA) {
            TileJob j = {mo, lxm, nullptr, 0, 222, csi_w0, 1024, csi_b0,
                         g_t1, 1024, tile * 64, 1};
            run_tile<3>(j, Xs, Ws);
        }
    }
    gbar();

    // ---------------- CSI layer 1 -------------------------------------------
    for (int tile = cta; tile < 16; tile += NCTA) {
        TileJob j = {g_t1, nullptr, nullptr, 0, 1024, csi_w1, 1024, csi_b1,
                     g_t2, 1024, tile * 64, 1};
        run_tile<0>(j, Xs, Ws);
    }
    gbar();

    // ---------------- CSI layer 2 (cell states) -----------------------------
    for (int tile = cta; tile < 32; tile += NCTA) {
        TileJob j = {g_t2, nullptr, nullptr, 0, 1024, csi_w2, 2048, csi_b2,
                     g_cell, 2048, tile * 64, 0};
        run_tile<0>(j, Xs, Ws);
    }
    gbar();

    // ---------------- init h0/h1/premo --------------------------------------
    for (int i = cta * NTHR + tid; i < 64 * 1024; i += NCTA * NTHR) {
        int r = i >> 10, c = i & 1023;
        g_h0[i] = g_cell[r * 2048 + c];
        g_h1[i] = g_cell[r * 2048 + 1024 + c];
    }
    for (int i = cta * NTHR + tid; i < 64 * 126; i += NCTA * NTHR) {
        g_premo[i] = mo[(size_t)i * 512 + 31];
    }
    gbar();

    // ---------------- time loop ---------------------------------------------
    for (int t = 0; t < TT; t++) {
        const float* xfix_t = g_xfix + (size_t)t * 64 * 256;

        // Phase A: gh0 (K split 512/512) + ine (K=382). 112 jobs, 1 wave.
        for (int job = cta; job < 112; job += NCTA) {
            if (job < 48) {
                TileJob j = {g_h0, nullptr, nullptr, 0, 512, whh0, 3072, bhh0,
                             g_gh0a, 3072, job * 64, 0};
                run_tile<0>(j, Xs, Ws);
            } else if (job < 96) {
                TileJob j = {g_h0, nullptr, nullptr, 512, 512, whh0, 3072,
                             nullptr, g_gh0b, 3072, (job - 48) * 64, 0};
                run_tile<0>(j, Xs, Ws);
            } else {
                TileJob j = {g_premo, xfix_t, nullptr, 0, 382, emb_w, 1024,
                             emb_b, g_ine, 1024, (job - 96) * 64, 1};
                run_tile<1>(j, Xs, Ws);
            }
        }
        gbar();

        // Phase B: gi0 = gx @ wih0, K split 512/512/382. 144 jobs, 1 wave.
        for (int job = cta; job < 144; job += NCTA) {
            if (job < 48) {
                TileJob j = {g_ine, g_premo, xfix_t, 0, 512, wih0, 3072, bih0,
                             g_gi0a, 3072, job * 64, 0};
                run_tile<2>(j, Xs, Ws);
            } else if (job < 96) {
                TileJob j = {g_ine, g_premo, xfix_t, 512, 512, wih0, 3072,
                             nullptr, g_gi0b, 3072, (job - 48) * 64, 0};
                run_tile<2>(j, Xs, Ws);
            } else {
                TileJob j = {g_ine, g_premo, xfix_t, 1024, 382, wih0, 3072,
                             nullptr, g_gi0c, 3072, (job - 96) * 64, 0};
                run_tile<2>(j, Xs, Ws);
            }
        }
        gbar();

        // Phase C: GRU0 gates -> h0 (in place), float4-vectorized.
        for (int i = cta * NTHR + tid; i < 64 * 256; i += NCTA * NTHR) {
            int r = i >> 8;
            int c4 = (i & 255) * 4;
            size_t base = (size_t)r * 3072 + c4;
            const float4* A0 = (const float4*)(g_gi0a + base);
            const float4* B0 = (const float4*)(g_gi0b + base);
            const float4* C0 = (const float4*)(g_gi0c + base);
            const float4* Ha = (const float4*)(g_gh0a + base);
            const float4* Hb = (const float4*)(g_gh0b + base);
            float4 ir = A0[0],   br_ = B0[0],   cr = C0[0];
            float4 iz = A0[256], bz = B0[256],  cz = C0[256];
            float4 in_ = A0[512], bn = B0[512], cn = C0[512];
            float4 hr = Ha[0],   hr2 = Hb[0];
            float4 hz = Ha[256], hz2 = Hb[256];
            float4 hn = Ha[512], hn2 = Hb[512];
            float4 ho = *(const float4*)(g_h0 + (size_t)r * 1024 + c4);
            float4 res;
            {
                float rg = sigm_f(ir.x + br_.x + cr.x + hr.x + hr2.x);
                float zg = sigm_f(iz.x + bz.x + cz.x + hz.x + hz2.x);
                float ng = tanhf(in_.x + bn.x + cn.x + rg * (hn.x + hn2.x));
                res.x = (1.f - zg) * ng + zg * ho.x;
            }
            {
                float rg = sigm_f(ir.y + br_.y + cr.y + hr.y + hr2.y);
                float zg = sigm_f(iz.y + bz.y + cz.y + hz.y + hz2.y);
                float ng = tanhf(in_.y + bn.y + cn.y + rg * (hn.y + hn2.y));
                res.y = (1.f - zg) * ng + zg * ho.y;
            }
            {
                float rg = sigm_f(ir.z + br_.z + cr.z + hr.z + hr2.z);
                float zg = sigm_f(iz.z + bz.z + cz.z + hz.z + hz2.z);
                float ng = tanhf(in_.z + bn.z + cn.z + rg * (hn.z + hn2.z));
                res.z = (1.f - zg) * ng + zg * ho.z;
            }
            {
                float rg = sigm_f(ir.w + br_.w + cr.w + hr.w + hr2.w);
                float zg = sigm_f(iz.w + bz.w + cz.w + hz.w + hz2.w);
                float ng = tanhf(in_.w + bn.w + cn.w + rg * (hn.w + hn2.w));
                res.w = (1.f - zg) * ng + zg * ho.w;
            }
            *(float4*)(g_h0 + (size_t)r * 1024 + c4) = res;
        }
        gbar();

        // Phase D: gi1 and gh1, K split 342/341/341 each. 288 jobs, 2 waves.
        for (int job = cta; job < 288; job += NCTA) {
            int g = job / 48, tl = (job % 48) * 64;
            TileJob j;
            switch (g) {
                case 0: j = {g_h0, nullptr, nullptr, 0, 342, wih1, 3072, bih1,
                             g_gi1a, 3072, tl, 0}; break;
                case 1: j = {g_h1, nullptr, nullptr, 0, 342, whh1, 3072, bhh1,
                             g_gh1a, 3072, tl, 0}; break;
                case 2: j = {g_h0, nullptr, nullptr, 342, 341, wih1, 3072,
                             nullptr, g_gi1b, 3072, tl, 0}; break;
                case 3: j = {g_h1, nullptr, nullptr, 342, 341, whh1, 3072,
                             nullptr, g_gh1b, 3072, tl, 0}; break;
                case 4: j = {g_h0, nullptr, nullptr, 683, 341, wih1, 3072,
                             nullptr, g_gi1c, 3072, tl, 0}; break;
                default: j = {g_h1, nullptr, nullptr, 683, 341, whh1, 3072,
                              nullptr, g_gh1c, 3072, tl, 0}; break;
            }
            run_tile<0>(j, Xs, Ws);
        }
        gbar();

        // Phase E: GRU1 gates + layernorm + pred (64 row-CTAs).
        if (cta < 64) {
            int r = cta;
            float* xs = pool;           // 1024
            float* red = pool + 1024;   // 256
            size_t rb = (size_t)r * 3072;
            float* hr = g_h1 + r * 1024;

            float lsum = 0.f;
            for (int c = tid; c < 1024; c += NTHR) {
                float gir_r = g_gi1a[rb + c] + g_gi1b[rb + c] + g_gi1c[rb + c];
                float ghr_r = g_gh1a[rb + c] + g_gh1b[rb + c] + g_gh1c[rb + c];
                float gir_z = g_gi1a[rb + c + 1024] + g_gi1b[rb + c + 1024] + g_gi1c[rb + c + 1024];
                float ghr_z = g_gh1a[rb + c + 1024] + g_gh1b[rb + c + 1024] + g_gh1c[rb + c + 1024];
                float gir_n = g_gi1a[rb + c + 2048] + g_gi1b[rb + c + 2048] + g_gi1c[rb + c + 2048];
                float ghr_n = g_gh1a[rb + c + 2048] + g_gh1b[rb + c + 2048] + g_gh1c[rb + c + 2048];
                float rg = sigm_f(gir_r + ghr_r);
                float zg = sigm_f(gir_z + ghr_z);
                float ng = tanhf(gir_n + rg * ghr_n);
                float hnew = (1.f - zg) * ng + zg * hr[c];
                hr[c] = hnew;
                xs[c] = hnew;
                lsum += hnew;
            }
            red[tid] = lsum;
            __syncthreads();
            for (int s = 128; s > 0; s >>= 1) {
                if (tid < s) red[tid] += red[tid + s];
                __syncthreads();
            }
            float mean = red[0] * (1.f / 1024.f);
            __syncthreads();
            float lv = 0.f;
            for (int c = tid; c < 1024; c += NTHR) {
                float d = xs[c] - mean;
                lv += d * d;
            }
            red[tid] = lv;
            __syncthreads();
            for (int s = 128; s > 0; s >>= 1) {
                if (tid < s) red[tid] += red[tid + s];
                __syncthreads();
            }
            float inv = rsqrtf(red[0] * (1.f / 1024.f) + 1e-5f);
            __syncthreads();
            for (int c = tid; c < 1024; c += NTHR)
                xs[c] = (xs[c] - mean) * inv * ln_g[c] + ln_b[c];
            __syncthreads();

            if (tid < 126) {
                float s0 = 0.f, s1 = 0.f, s2 = 0.f, s3 = 0.f;
                for (int k = 0; k < 1024; k += 4) {
                    s0 += xs[k + 0] * pred_w[(k + 0) * 126 + tid];
                    s1 += xs[k + 1] * pred_w[(k + 1) * 126 + tid];
                    s2 += xs[k + 2] * pred_w[(k + 2) * 126 + tid];
                    s3 += xs[k + 3] * pred_w[(k + 3) * 126 + tid];
                }
                float s = pred_b[tid] + ((s0 + s1) + (s2 + s3));
                g_premo[r * 126 + tid] = s;
                out[((size_t)r * 126 + tid) * 448 + t] = s;
            }
        }
        gbar();
    }
}

// ---------------------------------------------------------------------------
extern "C" void kernel_launch(void* const* d_in, const int* in_sizes, int n_in,
                              void* d_out, int out_size) {
    scan_kernel<<<NCTA, NTHR>>>(
        (const float*)d_in[0],  (const float*)d_in[1],  (const float*)d_in[2],
        (const int*)  d_in[3],  (const float*)d_in[4],  (const float*)d_in[5],
        (const float*)d_in[6],  (const float*)d_in[7],  (const float*)d_in[8],
        (const float*)d_in[9],  (const float*)d_in[10], (const float*)d_in[11],
        (const float*)d_in[12], (const float*)d_in[13], (const float*)d_in[14],
        (const float*)d_in[15], (const float*)d_in[16], (const float*)d_in[17],
        (const float*)d_in[18], (const float*)d_in[19], (const float*)d_in[20],
        (const float*)d_in[21], (const float*)d_in[22], (const float*)d_in[23],
        (const float*)d_in[24], (const float*)d_in[25], (const float*)d_in[26],
        (const float*)d_in[27], (const float*)d_in[28], (const float*)d_in[29],
        (float*)d_out);
}